// round 15
// baseline (speedup 1.0000x reference)
#include <cuda_runtime.h>
#include <cstdint>

#define D 128
#define C 64
#define EPSF 1e-5f
#define TGT 32              // targets per CTA -> grid = 16384/32 = 512
#define XS_STRIDE 132       // conflict-free row stride

// Device scratch (allocations forbidden)
__device__ float g_q[C * D];                 // EPS - prototype
__device__ unsigned int g_tickets;           // monotonic barrier counter (zero-init)

__device__ __forceinline__ void add_f32x2(unsigned long long& d,
                                          unsigned long long a,
                                          unsigned long long b) {
    asm("add.rn.f32x2 %0, %1, %2;" : "=l"(d) : "l"(a), "l"(b));
}
__device__ __forceinline__ void unpack2(float& lo, float& hi,
                                        unsigned long long v) {
    asm("mov.b64 {%0, %1}, %2;" : "=f"(lo), "=f"(hi) : "l"(v));
}

// Ticket barrier: correct across graph replays (counter only grows; cohort k
// = tickets (k-1)*nb+1 .. k*nb; wait until counter reaches end of own cohort).
// Call from ONE thread per CTA. Producer side must fence before arriving.
__device__ __forceinline__ void grid_barrier(unsigned int nb) {
    unsigned int t;
    asm volatile("atom.add.release.gpu.global.u32 %0, [%1], 1;"
                 : "=r"(t) : "l"(&g_tickets) : "memory");
    t += 1;
    unsigned int target = ((t + nb - 1) / nb) * nb;
    unsigned int cur;
    do {
        asm volatile("ld.acquire.gpu.global.u32 %0, [%1];"
                     : "=r"(cur) : "l"(&g_tickets) : "memory");
        if (cur >= target) break;
        __nanosleep(64);
    } while (true);
}

// ---------------------------------------------------------------------------
// Fused kernel: proto build (CTAs 0..63) + grid barrier + distance/softmax/NLL.
// grid 512, block 256, smem ~54KB -> 4 CTAs/SM; 64 regs -> RF exactly full.
// 592 residency slots >= 512 CTAs -> all co-resident (barrier is safe).
// ---------------------------------------------------------------------------
extern __shared__ float dynsmem[];

__global__ __launch_bounds__(256, 4) void k_fused(const float* __restrict__ x,
                                                  const int* __restrict__ y,
                                                  float* __restrict__ out,
                                                  int m, int nblocks) {
    float* xs = dynsmem;                   // 32 * 132 = 16.5 KB
    float* qs = xs + TGT * XS_STRIDE;      // 64 * 128 = 32 KB (scratch pre-barrier)
    __shared__ float spmax[16 * TGT];      // also proto 'partial' scratch
    __shared__ float spsum[16 * TGT];
    __shared__ float sdy[TGT];
    __shared__ int scnt;

    int tid = threadIdx.x;
    int bid = blockIdx.x;
    int i0  = bid * TGT;

    // ---- phase A (all CTAs): stage x target tile (32 x 128, float4) ----
    const float4* xg = (const float4*)(x + (size_t)(m + i0) * D);
#pragma unroll
    for (int k = 0; k < 4; k++) {
        int idx = tid + k * 256;
        int r = idx >> 5, c4 = idx & 31;
        *(float4*)&xs[r * XS_STRIDE + c4 * 4] = xg[r * 32 + c4];
    }

    if (bid == 0 && tid == 0) out[0] = 0.0f;

    // ---- phase B (CTAs 0..C-1): build prototype for class bid ----
    if (bid < C) {
        // scratch inside qs region (rewritten after barrier)
        unsigned short* list = (unsigned short*)qs;        // 4096 * 2B = 8KB
        float* partial = spmax;                            // 128 floats
        int c = bid;
        if (tid == 0) scnt = 0;
        __syncthreads();

#pragma unroll 8
        for (int i = tid; i < m; i += 256) {
            if (y[i] == c) {
                int p = atomicAdd(&scnt, 1);
                if (p < 4096) list[p] = (unsigned short)i;
            }
        }
        __syncthreads();
        int n = scnt < 4096 ? scnt : 4096;

        int j  = tid & (D - 1);
        int st = tid >> 7;                 // 2 streams
        float acc = 0.0f;
#pragma unroll 8
        for (int k = st; k < n; k += 2) {
            acc += x[(size_t)list[k] * D + j];
        }
        if (st == 1) partial[j] = acc;
        __syncthreads();
        if (st == 0) {
            float tot = acc + partial[j];
            float fc  = (n == 0) ? 1.0f : (float)n;
            g_q[c * D + j] = EPSF - tot / fc;
        }
    }
    __syncthreads();

    // ---- grid barrier (tid 0 arrives/spins; fence orders g_q / out writes) ----
    if (tid == 0) {
        __threadfence();
        grid_barrier((unsigned int)nblocks);
    }
    __syncthreads();

    // ---- phase C: stage q, then R13 mainloop ----
#pragma unroll
    for (int k = 0; k < 8; k++) {
        int idx = tid + k * 256;
        ((float4*)qs)[idx] = ((const float4*)g_q)[idx];
    }
    __syncthreads();

    int lane = tid & 31;
    int cg   = tid >> 5;                  // warp id 0..7
    int sub  = lane >> 4;                 // 0/1: class sub-group
    int trow = lane & 15;                 // target row 0..15
    int cb   = cg * 8 + sub * 4;          // first of this lane's 4 classes
    int sidx = cg * 2 + sub;              // class-subset index 0..15

    const ulonglong2* xr0 = (const ulonglong2*)&xs[trow * XS_STRIDE];
    const ulonglong2* xr1 = (const ulonglong2*)&xs[(trow + 16) * XS_STRIDE];
    const float* qb = &qs[cb * D];

    float acc[4][2];
#pragma unroll
    for (int k = 0; k < 4; k++) { acc[k][0] = 0.0f; acc[k][1] = 0.0f; }

#pragma unroll 2
    for (int j4 = 0; j4 < D / 4; j4++) {
        ulonglong2 xv0 = xr0[j4];
        ulonglong2 xv1 = xr1[j4];
#pragma unroll
        for (int cc = 0; cc < 4; cc++) {
            ulonglong2 qv = *(const ulonglong2*)&qb[cc * D + j4 * 4];
            unsigned long long a, b, e, f;
            add_f32x2(a, xv0.x, qv.x);     // t = x + (EPS - p)
            add_f32x2(b, xv0.y, qv.y);
            add_f32x2(e, xv1.x, qv.x);
            add_f32x2(f, xv1.y, qv.y);
            float lo, hi;
            unpack2(lo, hi, a);
            acc[cc][0] = fmaf(lo, fabsf(lo), acc[cc][0]);
            acc[cc][0] = fmaf(hi, fabsf(hi), acc[cc][0]);
            unpack2(lo, hi, b);
            acc[cc][0] = fmaf(lo, fabsf(lo), acc[cc][0]);
            acc[cc][0] = fmaf(hi, fabsf(hi), acc[cc][0]);
            unpack2(lo, hi, e);
            acc[cc][1] = fmaf(lo, fabsf(lo), acc[cc][1]);
            acc[cc][1] = fmaf(hi, fabsf(hi), acc[cc][1]);
            unpack2(lo, hi, f);
            acc[cc][1] = fmaf(lo, fabsf(lo), acc[cc][1]);
            acc[cc][1] = fmaf(hi, fabsf(hi), acc[cc][1]);
        }
    }

    // partial softmax over this lane's 4 classes, for both targets
    float dist[4][2];
    float pm0 = -1e30f, pm1 = -1e30f;
#pragma unroll
    for (int cc = 0; cc < 4; cc++) {
        float d0 = acc[cc][0] * (-1.0f / (float)D);
        float d1 = acc[cc][1] * (-1.0f / (float)D);
        dist[cc][0] = d0; dist[cc][1] = d1;
        pm0 = fmaxf(pm0, d0);
        pm1 = fmaxf(pm1, d1);
    }
    spmax[sidx * TGT + trow]      = pm0;
    spmax[sidx * TGT + trow + 16] = pm1;
    __syncthreads();

    float g0 = -1e30f, g1 = -1e30f;
#pragma unroll
    for (int k = 0; k < 16; k++) {
        g0 = fmaxf(g0, spmax[k * TGT + trow]);
        g1 = fmaxf(g1, spmax[k * TGT + trow + 16]);
    }
    float se0 = 0.0f, se1 = 0.0f;
#pragma unroll
    for (int cc = 0; cc < 4; cc++) {
        se0 += __expf(dist[cc][0] - g0);
        se1 += __expf(dist[cc][1] - g1);
    }
    spsum[sidx * TGT + trow]      = se0;
    spsum[sidx * TGT + trow + 16] = se1;

    int yc0 = y[m + i0 + trow];
    if (yc0 >= cb && yc0 < cb + 4) sdy[trow] = dist[yc0 - cb][0];
    int yc1 = y[m + i0 + trow + 16];
    if (yc1 >= cb && yc1 < cb + 4) sdy[trow + 16] = dist[yc1 - cb][1];
    __syncthreads();

    if (tid < TGT) {
        float tot = 0.0f, gm = -1e30f;
#pragma unroll
        for (int k = 0; k < 16; k++) {
            tot += spsum[k * TGT + tid];
            gm   = fmaxf(gm, spmax[k * TGT + tid]);
        }
        float v = -(sdy[tid] - gm - __logf(tot));
#pragma unroll
        for (int off = 16; off > 0; off >>= 1)
            v += __shfl_xor_sync(0xFFFFFFFFu, v, off);
        if (tid == 0) atomicAdd(out, v / (float)m);
    }
}

// ---------------------------------------------------------------------------
// launch
// ---------------------------------------------------------------------------
extern "C" void kernel_launch(void* const* d_in, const int* in_sizes, int n_in,
                              void* d_out, int out_size) {
    const float* x = (const float*)d_in[0];
    const int*   y = (const int*)d_in[1];
    int n = in_sizes[1];
    int m = n / 2;
    float* out = (float*)d_out;

    int nblocks = m / TGT;   // 512
    size_t dynbytes = (size_t)(TGT * XS_STRIDE + C * D) * sizeof(float);
    cudaFuncSetAttribute(k_fused, cudaFuncAttributeMaxDynamicSharedMemorySize,
                         (int)dynbytes);
    k_fused<<<nblocks, 256, dynbytes>>>(x, y, out, m, nblocks);
}

// round 16
// speedup vs baseline: 1.1730x; 1.1730x over previous
#include <cuda_runtime.h>
#include <cstdint>

#define D 128
#define C 64
#define EPSF 1e-5f
#define TGT 32              // targets per CTA -> grid = 16384/32 = 512
#define XS_STRIDE 132       // conflict-free row stride

// q[c][j] = EPS - prototype[c][j]   (device scratch; allocations forbidden)
__device__ float g_q[C * D];

__device__ __forceinline__ void add_f32x2(unsigned long long& d,
                                          unsigned long long a,
                                          unsigned long long b) {
    asm("add.rn.f32x2 %0, %1, %2;" : "=l"(d) : "l"(a), "l"(b));
}
__device__ __forceinline__ void unpack2(float& lo, float& hi,
                                        unsigned long long v) {
    asm("mov.b64 {%0, %1}, %2;" : "=f"(lo), "=f"(hi) : "l"(v));
}

// ---------------------------------------------------------------------------
// Kernel 1 (R12-proven): one CTA per class, block 512 = 4 row-streams.
// ---------------------------------------------------------------------------
__global__ __launch_bounds__(512) void k_accum(const float* __restrict__ x,
                                               const int* __restrict__ y,
                                               float* __restrict__ out,
                                               int m) {
    __shared__ unsigned short list[4096];
    __shared__ int cnt;
    __shared__ float partial[4 * D];

    int tid = threadIdx.x;
    int c   = blockIdx.x;
    if (tid == 0) cnt = 0;
    if (c == 0 && tid == 0) out[0] = 0.0f;
    __syncthreads();

#pragma unroll 8
    for (int i = tid; i < m; i += 512) {
        if (y[i] == c) {
            int p = atomicAdd(&cnt, 1);
            if (p < 4096) list[p] = (unsigned short)i;
        }
    }
    __syncthreads();
    int n = cnt < 4096 ? cnt : 4096;

    int j  = tid & (D - 1);
    int st = tid >> 7;                 // stream 0..3
    float acc = 0.0f;
#pragma unroll 8
    for (int k = st; k < n; k += 4) {
        acc += x[(size_t)list[k] * D + j];
    }
    partial[st * D + j] = acc;
    __syncthreads();
    if (tid < D) {
        float tot = partial[j] + partial[D + j] + partial[2 * D + j]
                  + partial[3 * D + j];
        float fc  = (n == 0) ? 1.0f : (float)n;
        g_q[c * D + j] = EPSF - tot / fc;
    }
}

// ---------------------------------------------------------------------------
// Kernel 2 (R13 structure; single change: q loads double-buffered so the
// 29-cyc LDS latency overlaps the 24-FMA block instead of serializing).
// block 256 = 8 warps; warp w: classes [8w, 8w+8); lane = sub*16 + trow;
// each lane: targets {trow, trow+16}, 4 classes. 1.5 fma-instr/element.
// ---------------------------------------------------------------------------
extern __shared__ float dynsmem[];

__global__ __launch_bounds__(256, 4) void k_loss(const float* __restrict__ x,
                                                 const int* __restrict__ y,
                                                 float* __restrict__ out,
                                                 int m) {
    float* xs = dynsmem;                   // 32 * 132 = 16.5 KB
    float* qs = xs + TGT * XS_STRIDE;      // 64 * 128 = 32 KB
    __shared__ float spmax[16 * TGT];
    __shared__ float spsum[16 * TGT];
    __shared__ float sdy[TGT];

    int tid = threadIdx.x;
    int i0  = blockIdx.x * TGT;

    // stage x target tile (32 x 128, coalesced float4)
    const float4* xg = (const float4*)(x + (size_t)(m + i0) * D);
#pragma unroll
    for (int k = 0; k < 4; k++) {
        int idx = tid + k * 256;
        int r = idx >> 5, c4 = idx & 31;
        *(float4*)&xs[r * XS_STRIDE + c4 * 4] = xg[r * 32 + c4];
    }
    // stage q
#pragma unroll
    for (int k = 0; k < 8; k++) {
        int idx = tid + k * 256;
        ((float4*)qs)[idx] = ((const float4*)g_q)[idx];
    }
    __syncthreads();

    int lane = tid & 31;
    int cg   = tid >> 5;                  // warp id 0..7
    int sub  = lane >> 4;                 // 0/1: class sub-group
    int trow = lane & 15;                 // target row 0..15
    int cb   = cg * 8 + sub * 4;          // first of this lane's 4 classes
    int sidx = cg * 2 + sub;              // class-subset index 0..15

    const ulonglong2* xr0 = (const ulonglong2*)&xs[trow * XS_STRIDE];
    const ulonglong2* xr1 = (const ulonglong2*)&xs[(trow + 16) * XS_STRIDE];
    const ulonglong2* qp0 = (const ulonglong2*)&qs[(cb + 0) * D];
    const ulonglong2* qp1 = (const ulonglong2*)&qs[(cb + 1) * D];
    const ulonglong2* qp2 = (const ulonglong2*)&qs[(cb + 2) * D];
    const ulonglong2* qp3 = (const ulonglong2*)&qs[(cb + 3) * D];

    float acc[4][2];
#pragma unroll
    for (int k = 0; k < 4; k++) { acc[k][0] = 0.0f; acc[k][1] = 0.0f; }

    // preload j4 = 0
    ulonglong2 qv0 = qp0[0], qv1 = qp1[0], qv2 = qp2[0], qv3 = qp3[0];

#pragma unroll 2
    for (int j4 = 0; j4 < D / 4; j4++) {
        ulonglong2 xv0 = xr0[j4];
        ulonglong2 xv1 = xr1[j4];
        // prefetch next iteration's q (wrap on last iter; value unused)
        int jn = (j4 + 1) & (D / 4 - 1);
        ulonglong2 nq0 = qp0[jn], nq1 = qp1[jn], nq2 = qp2[jn], nq3 = qp3[jn];

        ulonglong2 qv[4] = {qv0, qv1, qv2, qv3};
#pragma unroll
        for (int cc = 0; cc < 4; cc++) {
            unsigned long long a, b, e, f;
            add_f32x2(a, xv0.x, qv[cc].x);     // t = x + (EPS - p)
            add_f32x2(b, xv0.y, qv[cc].y);
            add_f32x2(e, xv1.x, qv[cc].x);
            add_f32x2(f, xv1.y, qv[cc].y);
            float lo, hi;
            unpack2(lo, hi, a);
            acc[cc][0] = fmaf(lo, fabsf(lo), acc[cc][0]);
            acc[cc][0] = fmaf(hi, fabsf(hi), acc[cc][0]);
            unpack2(lo, hi, b);
            acc[cc][0] = fmaf(lo, fabsf(lo), acc[cc][0]);
            acc[cc][0] = fmaf(hi, fabsf(hi), acc[cc][0]);
            unpack2(lo, hi, e);
            acc[cc][1] = fmaf(lo, fabsf(lo), acc[cc][1]);
            acc[cc][1] = fmaf(hi, fabsf(hi), acc[cc][1]);
            unpack2(lo, hi, f);
            acc[cc][1] = fmaf(lo, fabsf(lo), acc[cc][1]);
            acc[cc][1] = fmaf(hi, fabsf(hi), acc[cc][1]);
        }
        qv0 = nq0; qv1 = nq1; qv2 = nq2; qv3 = nq3;
    }

    // partial softmax over this lane's 4 classes, for both targets
    float dist[4][2];
    float pm0 = -1e30f, pm1 = -1e30f;
#pragma unroll
    for (int cc = 0; cc < 4; cc++) {
        float d0 = acc[cc][0] * (-1.0f / (float)D);
        float d1 = acc[cc][1] * (-1.0f / (float)D);
        dist[cc][0] = d0; dist[cc][1] = d1;
        pm0 = fmaxf(pm0, d0);
        pm1 = fmaxf(pm1, d1);
    }
    spmax[sidx * TGT + trow]      = pm0;
    spmax[sidx * TGT + trow + 16] = pm1;
    __syncthreads();

    float g0 = -1e30f, g1 = -1e30f;
#pragma unroll
    for (int k = 0; k < 16; k++) {
        g0 = fmaxf(g0, spmax[k * TGT + trow]);
        g1 = fmaxf(g1, spmax[k * TGT + trow + 16]);
    }
    float se0 = 0.0f, se1 = 0.0f;
#pragma unroll
    for (int cc = 0; cc < 4; cc++) {
        se0 += __expf(dist[cc][0] - g0);
        se1 += __expf(dist[cc][1] - g1);
    }
    spsum[sidx * TGT + trow]      = se0;
    spsum[sidx * TGT + trow + 16] = se1;

    int yc0 = y[m + i0 + trow];
    if (yc0 >= cb && yc0 < cb + 4) sdy[trow] = dist[yc0 - cb][0];
    int yc1 = y[m + i0 + trow + 16];
    if (yc1 >= cb && yc1 < cb + 4) sdy[trow + 16] = dist[yc1 - cb][1];
    __syncthreads();

    if (tid < TGT) {
        float tot = 0.0f, gm = -1e30f;
#pragma unroll
        for (int k = 0; k < 16; k++) {
            tot += spsum[k * TGT + tid];
            gm   = fmaxf(gm, spmax[k * TGT + tid]);
        }
        float v = -(sdy[tid] - gm - __logf(tot));
#pragma unroll
        for (int off = 16; off > 0; off >>= 1)
            v += __shfl_xor_sync(0xFFFFFFFFu, v, off);
        if (tid == 0) atomicAdd(out, v / (float)m);
    }
}

// ---------------------------------------------------------------------------
// launch
// ---------------------------------------------------------------------------
extern "C" void kernel_launch(void* const* d_in, const int* in_sizes, int n_in,
                              void* d_out, int out_size) {
    const float* x = (const float*)d_in[0];
    const int*   y = (const int*)d_in[1];
    int n = in_sizes[1];
    int m = n / 2;
    float* out = (float*)d_out;

    k_accum<<<C, 512>>>(x, y, out, m);

    size_t dynbytes = (size_t)(TGT * XS_STRIDE + C * D) * sizeof(float);
    cudaFuncSetAttribute(k_loss, cudaFuncAttributeMaxDynamicSharedMemorySize,
                         (int)dynbytes);
    k_loss<<<m / TGT, 256, dynbytes>>>(x, y, out, m);
}

// round 17
// speedup vs baseline: 1.2619x; 1.0757x over previous
#include <cuda_runtime.h>
#include <cstdint>

#define D 128
#define C 64
#define EPSF 1e-5f
#define TGT 32              // targets per CTA -> grid = 16384/32 = 512
#define XS_STRIDE 132       // conflict-free row stride

// q[c][j] = EPS - prototype[c][j]   (device scratch; allocations forbidden)
__device__ float g_q[C * D];

__device__ __forceinline__ void add_f32x2(unsigned long long& d,
                                          unsigned long long a,
                                          unsigned long long b) {
    asm("add.rn.f32x2 %0, %1, %2;" : "=l"(d) : "l"(a), "l"(b));
}
__device__ __forceinline__ void unpack2(float& lo, float& hi,
                                        unsigned long long v) {
    asm("mov.b64 {%0, %1}, %2;" : "=f"(lo), "=f"(hi) : "l"(v));
}

// ---------------------------------------------------------------------------
// Kernel 1: one CTA per class, block 1024 = 8 row-streams, unroll 8.
// Signals PDL dependents immediately (correctness is via griddepcontrol.wait
// in the consumer, which waits for this grid's completion).
// ---------------------------------------------------------------------------
__global__ __launch_bounds__(1024) void k_accum(const float* __restrict__ x,
                                                const int* __restrict__ y,
                                                float* __restrict__ out,
                                                int m) {
    asm volatile("griddepcontrol.launch_dependents;");

    __shared__ unsigned short list[4096];
    __shared__ int cnt;
    __shared__ float partial[8 * D];

    int tid = threadIdx.x;
    int c   = blockIdx.x;
    if (tid == 0) cnt = 0;
    if (c == 0 && tid == 0) out[0] = 0.0f;
    __syncthreads();

#pragma unroll 8
    for (int i = tid; i < m; i += 1024) {
        if (y[i] == c) {
            int p = atomicAdd(&cnt, 1);
            if (p < 4096) list[p] = (unsigned short)i;
        }
    }
    __syncthreads();
    int n = cnt < 4096 ? cnt : 4096;

    int j  = tid & (D - 1);
    int st = tid >> 7;                 // stream 0..7
    float acc = 0.0f;
#pragma unroll 8
    for (int k = st; k < n; k += 8) {
        acc += x[(size_t)list[k] * D + j];
    }
    partial[st * D + j] = acc;
    __syncthreads();
    if (tid < D) {
        float tot = 0.0f;
#pragma unroll
        for (int s = 0; s < 8; s++) tot += partial[s * D + j];
        float fc = (n == 0) ? 1.0f : (float)n;
        g_q[c * D + j] = EPSF - tot / fc;
    }
}

// ---------------------------------------------------------------------------
// Kernel 2 (R16-proven mainloop). PDL: stages x (independent of g_q) BEFORE
// griddepcontrol.wait, hiding k_accum + launch gap under the x prologue.
// ---------------------------------------------------------------------------
extern __shared__ float dynsmem[];

__global__ __launch_bounds__(256, 4) void k_loss(const float* __restrict__ x,
                                                 const int* __restrict__ y,
                                                 float* __restrict__ out,
                                                 int m) {
    float* xs = dynsmem;                   // 32 * 132 = 16.5 KB
    float* qs = xs + TGT * XS_STRIDE;      // 64 * 128 = 32 KB
    __shared__ float spmax[16 * TGT];
    __shared__ float spsum[16 * TGT];
    __shared__ float sdy[TGT];

    int tid = threadIdx.x;
    int i0  = blockIdx.x * TGT;

    // ---- stage x target tile (independent of k_accum results) ----
    const float4* xg = (const float4*)(x + (size_t)(m + i0) * D);
#pragma unroll
    for (int k = 0; k < 4; k++) {
        int idx = tid + k * 256;
        int r = idx >> 5, c4 = idx & 31;
        *(float4*)&xs[r * XS_STRIDE + c4 * 4] = xg[r * 32 + c4];
    }

    // ---- wait for k_accum's g_q / out-zero to be complete & visible ----
    asm volatile("griddepcontrol.wait;" ::: "memory");

    // ---- stage q ----
#pragma unroll
    for (int k = 0; k < 8; k++) {
        int idx = tid + k * 256;
        ((float4*)qs)[idx] = ((const float4*)g_q)[idx];
    }
    __syncthreads();

    int lane = tid & 31;
    int cg   = tid >> 5;                  // warp id 0..7
    int sub  = lane >> 4;                 // 0/1: class sub-group
    int trow = lane & 15;                 // target row 0..15
    int cb   = cg * 8 + sub * 4;          // first of this lane's 4 classes
    int sidx = cg * 2 + sub;              // class-subset index 0..15

    const ulonglong2* xr0 = (const ulonglong2*)&xs[trow * XS_STRIDE];
    const ulonglong2* xr1 = (const ulonglong2*)&xs[(trow + 16) * XS_STRIDE];
    const ulonglong2* qp0 = (const ulonglong2*)&qs[(cb + 0) * D];
    const ulonglong2* qp1 = (const ulonglong2*)&qs[(cb + 1) * D];
    const ulonglong2* qp2 = (const ulonglong2*)&qs[(cb + 2) * D];
    const ulonglong2* qp3 = (const ulonglong2*)&qs[(cb + 3) * D];

    float acc[4][2];
#pragma unroll
    for (int k = 0; k < 4; k++) { acc[k][0] = 0.0f; acc[k][1] = 0.0f; }

    // preload j4 = 0
    ulonglong2 qv0 = qp0[0], qv1 = qp1[0], qv2 = qp2[0], qv3 = qp3[0];

#pragma unroll 2
    for (int j4 = 0; j4 < D / 4; j4++) {
        ulonglong2 xv0 = xr0[j4];
        ulonglong2 xv1 = xr1[j4];
        int jn = (j4 + 1) & (D / 4 - 1);
        ulonglong2 nq0 = qp0[jn], nq1 = qp1[jn], nq2 = qp2[jn], nq3 = qp3[jn];

        ulonglong2 qv[4] = {qv0, qv1, qv2, qv3};
#pragma unroll
        for (int cc = 0; cc < 4; cc++) {
            unsigned long long a, b, e, f;
            add_f32x2(a, xv0.x, qv[cc].x);     // t = x + (EPS - p)
            add_f32x2(b, xv0.y, qv[cc].y);
            add_f32x2(e, xv1.x, qv[cc].x);
            add_f32x2(f, xv1.y, qv[cc].y);
            float lo, hi;
            unpack2(lo, hi, a);
            acc[cc][0] = fmaf(lo, fabsf(lo), acc[cc][0]);
            acc[cc][0] = fmaf(hi, fabsf(hi), acc[cc][0]);
            unpack2(lo, hi, b);
            acc[cc][0] = fmaf(lo, fabsf(lo), acc[cc][0]);
            acc[cc][0] = fmaf(hi, fabsf(hi), acc[cc][0]);
            unpack2(lo, hi, e);
            acc[cc][1] = fmaf(lo, fabsf(lo), acc[cc][1]);
            acc[cc][1] = fmaf(hi, fabsf(hi), acc[cc][1]);
            unpack2(lo, hi, f);
            acc[cc][1] = fmaf(lo, fabsf(lo), acc[cc][1]);
            acc[cc][1] = fmaf(hi, fabsf(hi), acc[cc][1]);
        }
        qv0 = nq0; qv1 = nq1; qv2 = nq2; qv3 = nq3;
    }

    // partial softmax over this lane's 4 classes, for both targets
    float dist[4][2];
    float pm0 = -1e30f, pm1 = -1e30f;
#pragma unroll
    for (int cc = 0; cc < 4; cc++) {
        float d0 = acc[cc][0] * (-1.0f / (float)D);
        float d1 = acc[cc][1] * (-1.0f / (float)D);
        dist[cc][0] = d0; dist[cc][1] = d1;
        pm0 = fmaxf(pm0, d0);
        pm1 = fmaxf(pm1, d1);
    }
    spmax[sidx * TGT + trow]      = pm0;
    spmax[sidx * TGT + trow + 16] = pm1;
    __syncthreads();

    float g0 = -1e30f, g1 = -1e30f;
#pragma unroll
    for (int k = 0; k < 16; k++) {
        g0 = fmaxf(g0, spmax[k * TGT + trow]);
        g1 = fmaxf(g1, spmax[k * TGT + trow + 16]);
    }
    float se0 = 0.0f, se1 = 0.0f;
#pragma unroll
    for (int cc = 0; cc < 4; cc++) {
        se0 += __expf(dist[cc][0] - g0);
        se1 += __expf(dist[cc][1] - g1);
    }
    spsum[sidx * TGT + trow]      = se0;
    spsum[sidx * TGT + trow + 16] = se1;

    int yc0 = y[m + i0 + trow];
    if (yc0 >= cb && yc0 < cb + 4) sdy[trow] = dist[yc0 - cb][0];
    int yc1 = y[m + i0 + trow + 16];
    if (yc1 >= cb && yc1 < cb + 4) sdy[trow + 16] = dist[yc1 - cb][1];
    __syncthreads();

    if (tid < TGT) {
        float tot = 0.0f, gm = -1e30f;
#pragma unroll
        for (int k = 0; k < 16; k++) {
            tot += spsum[k * TGT + tid];
            gm   = fmaxf(gm, spmax[k * TGT + tid]);
        }
        float v = -(sdy[tid] - gm - __logf(tot));
#pragma unroll
        for (int off = 16; off > 0; off >>= 1)
            v += __shfl_xor_sync(0xFFFFFFFFu, v, off);
        if (tid == 0) atomicAdd(out, v / (float)m);
    }
}

// ---------------------------------------------------------------------------
// launch: k_accum normally; k_loss via cudaLaunchKernelEx with PDL attribute.
// ---------------------------------------------------------------------------
extern "C" void kernel_launch(void* const* d_in, const int* in_sizes, int n_in,
                              void* d_out, int out_size) {
    const float* x = (const float*)d_in[0];
    const int*   y = (const int*)d_in[1];
    int n = in_sizes[1];
    int m = n / 2;
    float* out = (float*)d_out;

    k_accum<<<C, 1024>>>(x, y, out, m);

    size_t dynbytes = (size_t)(TGT * XS_STRIDE + C * D) * sizeof(float);
    cudaFuncSetAttribute(k_loss, cudaFuncAttributeMaxDynamicSharedMemorySize,
                         (int)dynbytes);

    cudaLaunchConfig_t cfg = {};
    cfg.gridDim = dim3(m / TGT, 1, 1);
    cfg.blockDim = dim3(256, 1, 1);
    cfg.dynamicSmemBytes = dynbytes;
    cfg.stream = 0;
    cudaLaunchAttribute attrs[1];
    attrs[0].id = cudaLaunchAttributeProgrammaticStreamSerialization;
    attrs[0].val.programmaticStreamSerializationAllowed = 1;
    cfg.attrs = attrs;
    cfg.numAttrs = 1;
    cudaLaunchKernelEx(&cfg, k_loss, x, y, out, m);
}